// round 7
// baseline (speedup 1.0000x reference)
#include <cuda_runtime.h>

#define NN 8192
#define KK 64
#define DD 256
#define HH 128
#define K1_GRID        148
#define K1_GEMM_BLOCKS 128
#define K1_THREADS     512
#define K1_FILLROWS    2560   // rows filled by the 20 aux blocks (80 MB)
#define AUX_ROWS       128    // rows per aux block (20 * 128 = 2560)

// ---- flat fp32 output layout (concat of reference tuple) ----
#define OFF_ADJ    0LL
#define OFF_FEAT   ((long long)NN * NN)
#define OFF_PROB   (OFF_FEAT + (long long)NN * DD)
#define OFF_PAIR   (OFF_PROB + (long long)NN * KK * 2)
#define OFF_BEFORE (OFF_PAIR + (long long)NN * KK * 2)
#define OFF_AFTER  (OFF_BEFORE + 1)
#define OFF_LEFT   (OFF_AFTER + 1)

// scratch: featW = feat @ W1   [N, 128]  (4 MB, L2-resident for edge gather)
__device__ float g_featW[(size_t)NN * HH];

// ---------------------------------------------------------------------------
// Kernel 1 (grid 148): blocks 0-127 = pure GEMM (featW = feat @ W1, W1 staged
// in 128KB smem, 4 rows/warp, fused feat copy). Blocks 128-147 = pure fill of
// adj rows [0, 2560) — they run on the 20 SMs the GEMM grid leaves idle, so
// the 80MB fill hides completely under the ~20us GEMM.
// ---------------------------------------------------------------------------
extern __shared__ float k1_smem[];

__global__ void __launch_bounds__(K1_THREADS) featw_kernel(const float* __restrict__ feat,
                                                           const float* __restrict__ W1,
                                                           float* __restrict__ out) {
    const int tid  = threadIdx.x;
    const int warp = tid >> 5;
    const int lane = tid & 31;

    if (blockIdx.x >= K1_GEMM_BLOCKS) {
        // ---- aux fill block: 128 adj rows = 4 MB of streaming zero stores
        const int fb = blockIdx.x - K1_GEMM_BLOCKS;
        float4* dst = reinterpret_cast<float4*>(out + (size_t)fb * AUX_ROWS * NN);
        const float4 z = make_float4(0.f, 0.f, 0.f, 0.f);
        const int total = AUX_ROWS * (NN / 4);           // 262144 float4
#pragma unroll 8
        for (int i = tid; i < total; i += K1_THREADS) __stcs(&dst[i], z);
        return;
    }

    float* sW   = k1_smem;                  // 256*128 floats = 128 KB
    float* srow = k1_smem + DD * HH;        // 16 warps * 4 rows * 256 = 64 KB

    // ---- stage full W1: 8192 float4, 16 per thread, coalesced
    {
        const float4* W14 = reinterpret_cast<const float4*>(W1);
        float4* sW4 = reinterpret_cast<float4*>(sW);
#pragma unroll
        for (int i = 0; i < 16; i++)
            sW4[i * K1_THREADS + tid] = W14[i * K1_THREADS + tid];
    }

    // ---- load this warp's 4 feat rows -> smem (+ streaming copy to out)
    const int row0 = blockIdx.x * 64 + warp * 4;
    float* rbase = srow + warp * 4 * DD;
#pragma unroll
    for (int r = 0; r < 4; r++) {
        const float4* f4 = reinterpret_cast<const float4*>(feat + (size_t)(row0 + r) * DD);
        float4 x0 = __ldcs(&f4[lane]), x1 = __ldcs(&f4[lane + 32]);
        reinterpret_cast<float4*>(rbase + r * DD)[lane]      = x0;
        reinterpret_cast<float4*>(rbase + r * DD)[lane + 32] = x1;
        float4* oc = reinterpret_cast<float4*>(out + OFF_FEAT + (size_t)(row0 + r) * DD);
        __stcs(&oc[lane], x0); __stcs(&oc[lane + 32], x1);
    }
    __syncthreads();   // W1 staged + rows written

    const float4* sW4 = reinterpret_cast<const float4*>(sW);
    const float* r0 = rbase;
    const float* r1 = rbase + DD;
    const float* r2 = rbase + 2 * DD;
    const float* r3 = rbase + 3 * DD;

    float4 acc0 = make_float4(0.f, 0.f, 0.f, 0.f);
    float4 acc1 = make_float4(0.f, 0.f, 0.f, 0.f);
    float4 acc2 = make_float4(0.f, 0.f, 0.f, 0.f);
    float4 acc3 = make_float4(0.f, 0.f, 0.f, 0.f);
#pragma unroll 4
    for (int k = 0; k < DD; k++) {
        float4 wv = sW4[k * 32 + lane];
        float s0 = r0[k], s1 = r1[k], s2 = r2[k], s3 = r3[k];
        acc0.x = fmaf(s0, wv.x, acc0.x); acc0.y = fmaf(s0, wv.y, acc0.y);
        acc0.z = fmaf(s0, wv.z, acc0.z); acc0.w = fmaf(s0, wv.w, acc0.w);
        acc1.x = fmaf(s1, wv.x, acc1.x); acc1.y = fmaf(s1, wv.y, acc1.y);
        acc1.z = fmaf(s1, wv.z, acc1.z); acc1.w = fmaf(s1, wv.w, acc1.w);
        acc2.x = fmaf(s2, wv.x, acc2.x); acc2.y = fmaf(s2, wv.y, acc2.y);
        acc2.z = fmaf(s2, wv.z, acc2.z); acc2.w = fmaf(s2, wv.w, acc2.w);
        acc3.x = fmaf(s3, wv.x, acc3.x); acc3.y = fmaf(s3, wv.y, acc3.y);
        acc3.z = fmaf(s3, wv.z, acc3.z); acc3.w = fmaf(s3, wv.w, acc3.w);
    }
    reinterpret_cast<float4*>(g_featW + (size_t)(row0 + 0) * HH)[lane] = acc0;
    reinterpret_cast<float4*>(g_featW + (size_t)(row0 + 1) * HH)[lane] = acc1;
    reinterpret_cast<float4*>(g_featW + (size_t)(row0 + 2) * HH)[lane] = acc2;
    reinterpret_cast<float4*>(g_featW + (size_t)(row0 + 3) * HH)[lane] = acc3;

    if (blockIdx.x == 0 && tid == 0) {
        out[OFF_BEFORE] = 64.0f;
        out[OFF_AFTER]  = 0.0f;
    }
}

// ---------------------------------------------------------------------------
// Kernel 2: WARP-PER-ROW, zero __syncthreads. 8-deep gather flights (R5-
// proven). Selection-based multi-reduce: 9 shuffles/batch, summation tree
// identical to the validated butterfly (bit-identical D). Lane->edge harvest
// map: e(l) = 4*bit2(l) + 2*bit3(l) + bit4(l), lanes with (l&3)==0 write.
// ---------------------------------------------------------------------------
__global__ void __launch_bounds__(256) edge_kernel(const float* __restrict__ adj,
                                                   const int*   __restrict__ nbr,
                                                   const float* __restrict__ b1,
                                                   const float* __restrict__ prelu_a,
                                                   const float* __restrict__ W2,
                                                   const float* __restrict__ b2,
                                                   float* __restrict__ out) {
    __shared__ int   snbr[8][KK];
    __shared__ __align__(16) float sD[8][KK];   // D values, then overwritten by p1

    const int tid  = threadIdx.x;
    const int warp = tid >> 5;
    const int lane = tid & 31;
    const int row  = blockIdx.x * 8 + warp;

    const int nlo = __ldg(&nbr[row * KK + lane]);
    const int nhi = __ldg(&nbr[row * KK + lane + 32]);
    snbr[warp][lane]      = nlo;
    snbr[warp][lane + 32] = nhi;
    const float vlo = __ldg(adj + (size_t)row * NN + nlo);
    const float vhi = __ldg(adj + (size_t)row * NN + nhi);

    const float4* fW4 = reinterpret_cast<const float4*>(g_featW);
    float4 fs = fW4[(size_t)row * 32 + lane];
    {
        float4 bb = __ldg(&reinterpret_cast<const float4*>(b1)[lane]);
        fs.x += bb.x; fs.y += bb.y; fs.z += bb.z; fs.w += bb.w;
    }

    // streaming zero-fill of own row (rows not covered by kernel 1 aux blocks)
    if (row >= K1_FILLROWS) {
        float4* orow = reinterpret_cast<float4*>(out + (size_t)row * NN);
        const float4 z = make_float4(0.f, 0.f, 0.f, 0.f);
#pragma unroll
        for (int i = 0; i < 64; i++) __stcs(&orow[i * 32 + lane], z);
    }

    // pair_list
    {
        float2* pp = reinterpret_cast<float2*>(out + OFF_PAIR) + (long long)row * KK;
        __stcs(&pp[lane],      make_float2((float)row, (float)nlo));
        __stcs(&pp[lane + 32], make_float2((float)row, (float)nhi));
    }

    const int j0 = lane * 4;
    const float a0 = __ldg(&prelu_a[j0 + 0]), a1 = __ldg(&prelu_a[j0 + 1]),
                a2 = __ldg(&prelu_a[j0 + 2]), a3 = __ldg(&prelu_a[j0 + 3]);
    const float wd0 = __ldg(&W2[(j0 + 0) * 2 + 1]) - __ldg(&W2[(j0 + 0) * 2]);
    const float wd1 = __ldg(&W2[(j0 + 1) * 2 + 1]) - __ldg(&W2[(j0 + 1) * 2]);
    const float wd2 = __ldg(&W2[(j0 + 2) * 2 + 1]) - __ldg(&W2[(j0 + 2) * 2]);
    const float wd3 = __ldg(&W2[(j0 + 3) * 2 + 1]) - __ldg(&W2[(j0 + 3) * 2]);
    const float b2d = __ldg(&b2[1]) - __ldg(&b2[0]);

    const bool h16 = (lane & 16) != 0;
    const bool h8  = (lane & 8)  != 0;
    const bool h4  = (lane & 4)  != 0;
    const int  eidx = ((lane >> 2) & 1) * 4 + ((lane >> 3) & 1) * 2 + ((lane >> 4) & 1);
    const bool writer = (lane & 3) == 0;

    __syncwarp();   // snbr visible

#pragma unroll
    for (int b = 0; b < 8; b++) {          // 8 batches of 8 edges, 8-deep gather
        float4 fd[8];
#pragma unroll
        for (int e = 0; e < 8; e++)
            fd[e] = fW4[(size_t)snbr[warp][b * 8 + e] * 32 + lane];

        float dd[8];
#pragma unroll
        for (int e = 0; e < 8; e++) {
            float h0 = fs.x - fd[e].x, h1 = fs.y - fd[e].y;
            float h2 = fs.z - fd[e].z, h3 = fs.w - fd[e].w;
            h0 = (h0 >= 0.f) ? h0 : a0 * h0;
            h1 = (h1 >= 0.f) ? h1 : a1 * h1;
            h2 = (h2 >= 0.f) ? h2 : a2 * h2;
            h3 = (h3 >= 0.f) ? h3 : a3 * h3;
            dd[e] = h0 * wd0 + h1 * wd1 + h2 * wd2 + h3 * wd3;
        }

        // selection multi-reduce (same tree as butterfly: own + recv each step)
        float w[4];
#pragma unroll
        for (int i = 0; i < 4; i++) {
            float send = h16 ? dd[2 * i] : dd[2 * i + 1];
            float recv = __shfl_xor_sync(0xffffffffu, send, 16);
            w[i] = (h16 ? dd[2 * i + 1] : dd[2 * i]) + recv;
        }
        float x0, x1;
        {
            float send = h8 ? w[0] : w[1];
            float recv = __shfl_xor_sync(0xffffffffu, send, 8);
            x0 = (h8 ? w[1] : w[0]) + recv;
            send = h8 ? w[2] : w[3];
            recv = __shfl_xor_sync(0xffffffffu, send, 8);
            x1 = (h8 ? w[3] : w[2]) + recv;
        }
        float y;
        {
            float send = h4 ? x0 : x1;
            float recv = __shfl_xor_sync(0xffffffffu, send, 4);
            y = (h4 ? x1 : x0) + recv;
        }
        y += __shfl_xor_sync(0xffffffffu, y, 2);
        y += __shfl_xor_sync(0xffffffffu, y, 1);

        if (writer) sD[warp][b * 8 + eidx] = y;
    }
    __syncwarp();

    // sigmoid probs (p0 = sigmoid(-D) = e * p1; validated approximation)
    const float D_lo = sD[warp][lane]      + b2d;
    const float D_hi = sD[warp][lane + 32] + b2d;
    const float e_lo = expf(-D_lo), e_hi = expf(-D_hi);
    const float p1_lo = 1.0f / (1.0f + e_lo);
    const float p1_hi = 1.0f / (1.0f + e_hi);
    const float p0_lo = e_lo * p1_lo;
    const float p0_hi = e_hi * p1_hi;
    {
        float2* pr = reinterpret_cast<float2*>(out + OFF_PROB) + (long long)row * KK;
        __stcs(&pr[lane],      make_float2(p0_lo, p1_lo));
        __stcs(&pr[lane + 32], make_float2(p0_hi, p1_hi));
    }
    sD[warp][lane]      = p1_lo;    // reuse as sp1 (own-slot read->write, safe)
    sD[warp][lane + 32] = p1_hi;
    __syncwarp();

    // stable ascending rank, vectorized over sp1 (16 x LDS.128)
    int rank_lo = 0, rank_hi = 0;
    const float4* sp4 = reinterpret_cast<const float4*>(&sD[warp][0]);
#pragma unroll
    for (int q = 0; q < 16; q++) {
        float4 v = sp4[q];
        const int j = q * 4;
        rank_lo += (v.x < p1_lo) || (v.x == p1_lo && (j + 0) < lane);
        rank_lo += (v.y < p1_lo) || (v.y == p1_lo && (j + 1) < lane);
        rank_lo += (v.z < p1_lo) || (v.z == p1_lo && (j + 2) < lane);
        rank_lo += (v.w < p1_lo) || (v.w == p1_lo && (j + 3) < lane);
        rank_hi += (v.x < p1_hi) || (v.x == p1_hi && (j + 0) < lane + 32);
        rank_hi += (v.y < p1_hi) || (v.y == p1_hi && (j + 1) < lane + 32);
        rank_hi += (v.z < p1_hi) || (v.z == p1_hi && (j + 2) < lane + 32);
        rank_hi += (v.w < p1_hi) || (v.w == p1_hi && (j + 3) < lane + 32);
    }
    const int keep_lo = rank_lo >= 32;
    const int keep_hi = rank_hi >= 32;

    if (keep_lo)
        __stcs(&out[OFF_LEFT + (long long)row * 32 + (rank_lo - 32)],
               (float)(row * KK + lane));
    if (keep_hi)
        __stcs(&out[OFF_LEFT + (long long)row * 32 + (rank_hi - 32)],
               (float)(row * KK + lane + 32));

    // degree + nonzero-kept count
    float v = (keep_lo ? vlo : 0.f) + (keep_hi ? vhi : 0.f);
    float c = (keep_lo && vlo != 0.f ? 1.f : 0.f) + (keep_hi && vhi != 0.f ? 1.f : 0.f);
#pragma unroll
    for (int off = 16; off; off >>= 1) {
        v += __shfl_xor_sync(0xffffffffu, v, off);
        c += __shfl_xor_sync(0xffffffffu, c, off);
    }
    if (lane == 0) atomicAdd(out + OFF_AFTER, c * (1.0f / 8192.0f));

    __syncwarp();   // order own-row zero-fill before scatter

    const float inv = 1.0f / (v + 1e-6f);
    if (keep_lo) __stcs(&out[(size_t)row * NN + nlo], vlo * inv);
    if (keep_hi) __stcs(&out[(size_t)row * NN + nhi], vhi * inv);
}

// ---------------------------------------------------------------------------
extern "C" void kernel_launch(void* const* d_in, const int* in_sizes, int n_in,
                              void* d_out, int out_size) {
    const float* adj = nullptr; const float* feat = nullptr;
    const int*   nbr = nullptr; const float* W1   = nullptr;
    const float* b1  = nullptr; const float* pa   = nullptr;
    const float* W2  = nullptr; const float* b2   = nullptr;

    for (int i = 0; i < n_in; i++) {
        long long s = in_sizes[i];
        if      (s == (long long)NN * NN) adj  = (const float*)d_in[i];
        else if (s == (long long)NN * DD) feat = (const float*)d_in[i];
        else if (s == (long long)NN * KK) nbr  = (const int*)d_in[i];
        else if (s == (long long)DD * HH) W1   = (const float*)d_in[i];
        else if (s == HH) { if (!b1) b1 = (const float*)d_in[i];
                            else     pa = (const float*)d_in[i]; }
        else if (s == HH * 2) W2 = (const float*)d_in[i];
        else if (s == 2)      b2 = (const float*)d_in[i];
    }

    float* out = (float*)d_out;
    const int k1_smem_bytes = (DD * HH + 16 * 4 * DD) * (int)sizeof(float); // 192 KB
    static int attr_done = 0;
    if (!attr_done) {
        cudaFuncSetAttribute(featw_kernel,
                             cudaFuncAttributeMaxDynamicSharedMemorySize, k1_smem_bytes);
        attr_done = 1;
    }
    featw_kernel<<<K1_GRID, K1_THREADS, k1_smem_bytes>>>(feat, W1, out);
    edge_kernel<<<NN / 8, 256>>>(adj, nbr, b1, pa, W2, b2, out);
}

// round 8
// speedup vs baseline: 1.6893x; 1.6893x over previous
#include <cuda_runtime.h>

#define NN 8192
#define KK 64
#define DD 256
#define HH 128
#define K1_BLOCKS   128
#define K1_THREADS  512
#define K1_FILLROWS 3072   // rows [0,3072) filled by k1 (24 rows/block, 96 MB)

// ---- flat fp32 output layout (concat of reference tuple) ----
#define OFF_ADJ    0LL
#define OFF_FEAT   ((long long)NN * NN)
#define OFF_PROB   (OFF_FEAT + (long long)NN * DD)
#define OFF_PAIR   (OFF_PROB + (long long)NN * KK * 2)
#define OFF_BEFORE (OFF_PAIR + (long long)NN * KK * 2)
#define OFF_AFTER  (OFF_BEFORE + 1)
#define OFF_LEFT   (OFF_AFTER + 1)

// scratch: featW = feat @ W1   [N, 128]  (4 MB, L2-resident for edge gather)
__device__ float g_featW[(size_t)NN * HH];

// ---------------------------------------------------------------------------
// Kernel 1: featW = feat @ W1 with the 96MB zero-fill SOFTWARE-PIPELINED into
// the FMA loop (one STG.128 every other k-iteration; stores drain in the FMA
// latency shadow instead of a serial fill phase). W1 staged in 128KB smem,
// 4 rows/warp, fused feat copy.
// ---------------------------------------------------------------------------
extern __shared__ float k1_smem[];

__global__ void __launch_bounds__(K1_THREADS) featw_kernel(const float* __restrict__ feat,
                                                           const float* __restrict__ W1,
                                                           float* __restrict__ out) {
    float* sW   = k1_smem;                  // 256*128 floats = 128 KB
    float* srow = k1_smem + DD * HH;        // 16 warps * 4 rows * 256 = 64 KB

    const int tid  = threadIdx.x;
    const int warp = tid >> 5;
    const int lane = tid & 31;

    // ---- stage full W1: 8192 float4, 16 per thread, coalesced
    {
        const float4* W14 = reinterpret_cast<const float4*>(W1);
        float4* sW4 = reinterpret_cast<float4*>(sW);
#pragma unroll
        for (int i = 0; i < 16; i++)
            sW4[i * K1_THREADS + tid] = W14[i * K1_THREADS + tid];
    }

    // ---- load this warp's 4 feat rows -> smem (+ streaming copy to out)
    const int row0 = blockIdx.x * 64 + warp * 4;
    float* rbase = srow + warp * 4 * DD;
#pragma unroll
    for (int r = 0; r < 4; r++) {
        const float4* f4 = reinterpret_cast<const float4*>(feat + (size_t)(row0 + r) * DD);
        float4 x0 = __ldcs(&f4[lane]), x1 = __ldcs(&f4[lane + 32]);
        reinterpret_cast<float4*>(rbase + r * DD)[lane]      = x0;
        reinterpret_cast<float4*>(rbase + r * DD)[lane + 32] = x1;
        float4* oc = reinterpret_cast<float4*>(out + OFF_FEAT + (size_t)(row0 + r) * DD);
        __stcs(&oc[lane], x0); __stcs(&oc[lane + 32], x1);
    }
    __syncthreads();   // W1 staged + rows written

    const float4* sW4 = reinterpret_cast<const float4*>(sW);
    const float* r0 = rbase;
    const float* r1 = rbase + DD;
    const float* r2 = rbase + 2 * DD;
    const float* r3 = rbase + 3 * DD;

    // fill target: 24 adj rows per block = 49152 float4 = 96 per thread
    float4* fdst = reinterpret_cast<float4*>(
        out + (size_t)blockIdx.x * (K1_FILLROWS / K1_BLOCKS) * NN);
    const float4 z = make_float4(0.f, 0.f, 0.f, 0.f);

    float4 acc0 = make_float4(0.f, 0.f, 0.f, 0.f);
    float4 acc1 = make_float4(0.f, 0.f, 0.f, 0.f);
    float4 acc2 = make_float4(0.f, 0.f, 0.f, 0.f);
    float4 acc3 = make_float4(0.f, 0.f, 0.f, 0.f);
#pragma unroll 4
    for (int k = 0; k < DD; k++) {
        float4 wv = sW4[k * 32 + lane];
        float s0 = r0[k], s1 = r1[k], s2 = r2[k], s3 = r3[k];
        acc0.x = fmaf(s0, wv.x, acc0.x); acc0.y = fmaf(s0, wv.y, acc0.y);
        acc0.z = fmaf(s0, wv.z, acc0.z); acc0.w = fmaf(s0, wv.w, acc0.w);
        acc1.x = fmaf(s1, wv.x, acc1.x); acc1.y = fmaf(s1, wv.y, acc1.y);
        acc1.z = fmaf(s1, wv.z, acc1.z); acc1.w = fmaf(s1, wv.w, acc1.w);
        acc2.x = fmaf(s2, wv.x, acc2.x); acc2.y = fmaf(s2, wv.y, acc2.y);
        acc2.z = fmaf(s2, wv.z, acc2.z); acc2.w = fmaf(s2, wv.w, acc2.w);
        acc3.x = fmaf(s3, wv.x, acc3.x); acc3.y = fmaf(s3, wv.y, acc3.y);
        acc3.z = fmaf(s3, wv.z, acc3.z); acc3.w = fmaf(s3, wv.w, acc3.w);
        // pipelined fill: 96 stores spread over the first 192 iterations
        if (k < 192 && (k & 1)) {
            __stcs(&fdst[(size_t)(k >> 1) * K1_THREADS + tid], z);
        }
    }
    reinterpret_cast<float4*>(g_featW + (size_t)(row0 + 0) * HH)[lane] = acc0;
    reinterpret_cast<float4*>(g_featW + (size_t)(row0 + 1) * HH)[lane] = acc1;
    reinterpret_cast<float4*>(g_featW + (size_t)(row0 + 2) * HH)[lane] = acc2;
    reinterpret_cast<float4*>(g_featW + (size_t)(row0 + 3) * HH)[lane] = acc3;

    if (blockIdx.x == 0 && tid == 0) {
        out[OFF_BEFORE] = 64.0f;
        out[OFF_AFTER]  = 0.0f;
    }
}

// ---------------------------------------------------------------------------
// Kernel 2: WARP-PER-ROW, zero __syncthreads. Selection-based multi-reduce
// (validated R7, bit-path identical). The 32KB own-row zero-fill is pipelined
// into the 8 gather batches: 8 STG.128 issued right after each batch's 8
// LDG.128 gathers, draining in the gather latency shadow.
// ---------------------------------------------------------------------------
__global__ void __launch_bounds__(256) edge_kernel(const float* __restrict__ adj,
                                                   const int*   __restrict__ nbr,
                                                   const float* __restrict__ b1,
                                                   const float* __restrict__ prelu_a,
                                                   const float* __restrict__ W2,
                                                   const float* __restrict__ b2,
                                                   float* __restrict__ out) {
    __shared__ int   snbr[8][KK];
    __shared__ __align__(16) float sD[8][KK];   // D values, then reused as p1

    const int tid  = threadIdx.x;
    const int warp = tid >> 5;
    const int lane = tid & 31;
    const int row  = blockIdx.x * 8 + warp;

    const int nlo = __ldg(&nbr[row * KK + lane]);
    const int nhi = __ldg(&nbr[row * KK + lane + 32]);
    snbr[warp][lane]      = nlo;
    snbr[warp][lane + 32] = nhi;
    const float vlo = __ldg(adj + (size_t)row * NN + nlo);
    const float vhi = __ldg(adj + (size_t)row * NN + nhi);

    const float4* fW4 = reinterpret_cast<const float4*>(g_featW);
    float4 fs = fW4[(size_t)row * 32 + lane];
    {
        float4 bb = __ldg(&reinterpret_cast<const float4*>(b1)[lane]);
        fs.x += bb.x; fs.y += bb.y; fs.z += bb.z; fs.w += bb.w;
    }

    // pair_list (independent)
    {
        float2* pp = reinterpret_cast<float2*>(out + OFF_PAIR) + (long long)row * KK;
        __stcs(&pp[lane],      make_float2((float)row, (float)nlo));
        __stcs(&pp[lane + 32], make_float2((float)row, (float)nhi));
    }

    const int j0 = lane * 4;
    const float a0 = __ldg(&prelu_a[j0 + 0]), a1 = __ldg(&prelu_a[j0 + 1]),
                a2 = __ldg(&prelu_a[j0 + 2]), a3 = __ldg(&prelu_a[j0 + 3]);
    const float wd0 = __ldg(&W2[(j0 + 0) * 2 + 1]) - __ldg(&W2[(j0 + 0) * 2]);
    const float wd1 = __ldg(&W2[(j0 + 1) * 2 + 1]) - __ldg(&W2[(j0 + 1) * 2]);
    const float wd2 = __ldg(&W2[(j0 + 2) * 2 + 1]) - __ldg(&W2[(j0 + 2) * 2]);
    const float wd3 = __ldg(&W2[(j0 + 3) * 2 + 1]) - __ldg(&W2[(j0 + 3) * 2]);
    const float b2d = __ldg(&b2[1]) - __ldg(&b2[0]);

    const bool h16 = (lane & 16) != 0;
    const bool h8  = (lane & 8)  != 0;
    const bool h4  = (lane & 4)  != 0;
    const int  eidx = ((lane >> 2) & 1) * 4 + ((lane >> 3) & 1) * 2 + ((lane >> 4) & 1);
    const bool writer = (lane & 3) == 0;

    const bool dofill = (row >= K1_FILLROWS);
    float4* orow = reinterpret_cast<float4*>(out + (size_t)row * NN);
    const float4 z = make_float4(0.f, 0.f, 0.f, 0.f);

    __syncwarp();   // snbr visible

#pragma unroll
    for (int b = 0; b < 8; b++) {          // 8 batches of 8 edges, 8-deep gather
        float4 fd[8];
#pragma unroll
        for (int e = 0; e < 8; e++)
            fd[e] = fW4[(size_t)snbr[warp][b * 8 + e] * 32 + lane];

        // pipelined fill: 8 row-chunks (4KB) while the gathers are in flight
        if (dofill) {
#pragma unroll
            for (int s = 0; s < 8; s++)
                __stcs(&orow[(b * 8 + s) * 32 + lane], z);
        }

        float dd[8];
#pragma unroll
        for (int e = 0; e < 8; e++) {
            float h0 = fs.x - fd[e].x, h1 = fs.y - fd[e].y;
            float h2 = fs.z - fd[e].z, h3 = fs.w - fd[e].w;
            h0 = (h0 >= 0.f) ? h0 : a0 * h0;
            h1 = (h1 >= 0.f) ? h1 : a1 * h1;
            h2 = (h2 >= 0.f) ? h2 : a2 * h2;
            h3 = (h3 >= 0.f) ? h3 : a3 * h3;
            dd[e] = h0 * wd0 + h1 * wd1 + h2 * wd2 + h3 * wd3;
        }

        // selection multi-reduce (same summation tree as butterfly)
        float w[4];
#pragma unroll
        for (int i = 0; i < 4; i++) {
            float send = h16 ? dd[2 * i] : dd[2 * i + 1];
            float recv = __shfl_xor_sync(0xffffffffu, send, 16);
            w[i] = (h16 ? dd[2 * i + 1] : dd[2 * i]) + recv;
        }
        float x0, x1;
        {
            float send = h8 ? w[0] : w[1];
            float recv = __shfl_xor_sync(0xffffffffu, send, 8);
            x0 = (h8 ? w[1] : w[0]) + recv;
            send = h8 ? w[2] : w[3];
            recv = __shfl_xor_sync(0xffffffffu, send, 8);
            x1 = (h8 ? w[3] : w[2]) + recv;
        }
        float y;
        {
            float send = h4 ? x0 : x1;
            float recv = __shfl_xor_sync(0xffffffffu, send, 4);
            y = (h4 ? x1 : x0) + recv;
        }
        y += __shfl_xor_sync(0xffffffffu, y, 2);
        y += __shfl_xor_sync(0xffffffffu, y, 1);

        if (writer) sD[warp][b * 8 + eidx] = y;
    }
    __syncwarp();

    // sigmoid probs (p0 = sigmoid(-D) = e * p1)
    const float D_lo = sD[warp][lane]      + b2d;
    const float D_hi = sD[warp][lane + 32] + b2d;
    const float e_lo = expf(-D_lo), e_hi = expf(-D_hi);
    const float p1_lo = 1.0f / (1.0f + e_lo);
    const float p1_hi = 1.0f / (1.0f + e_hi);
    const float p0_lo = e_lo * p1_lo;
    const float p0_hi = e_hi * p1_hi;
    {
        float2* pr = reinterpret_cast<float2*>(out + OFF_PROB) + (long long)row * KK;
        __stcs(&pr[lane],      make_float2(p0_lo, p1_lo));
        __stcs(&pr[lane + 32], make_float2(p0_hi, p1_hi));
    }
    sD[warp][lane]      = p1_lo;    // reuse as sp1 (own-slot rewrite, safe)
    sD[warp][lane + 32] = p1_hi;
    __syncwarp();

    // stable ascending rank, vectorized (16 x LDS.128)
    int rank_lo = 0, rank_hi = 0;
    const float4* sp4 = reinterpret_cast<const float4*>(&sD[warp][0]);
#pragma unroll
    for (int q = 0; q < 16; q++) {
        float4 v = sp4[q];
        const int j = q * 4;
        rank_lo += (v.x < p1_lo) || (v.x == p1_lo && (j + 0) < lane);
        rank_lo += (v.y < p1_lo) || (v.y == p1_lo && (j + 1) < lane);
        rank_lo += (v.z < p1_lo) || (v.z == p1_lo && (j + 2) < lane);
        rank_lo += (v.w < p1_lo) || (v.w == p1_lo && (j + 3) < lane);
        rank_hi += (v.x < p1_hi) || (v.x == p1_hi && (j + 0) < lane + 32);
        rank_hi += (v.y < p1_hi) || (v.y == p1_hi && (j + 1) < lane + 32);
        rank_hi += (v.z < p1_hi) || (v.z == p1_hi && (j + 2) < lane + 32);
        rank_hi += (v.w < p1_hi) || (v.w == p1_hi && (j + 3) < lane + 32);
    }
    const int keep_lo = rank_lo >= 32;
    const int keep_hi = rank_hi >= 32;

    if (keep_lo)
        __stcs(&out[OFF_LEFT + (long long)row * 32 + (rank_lo - 32)],
               (float)(row * KK + lane));
    if (keep_hi)
        __stcs(&out[OFF_LEFT + (long long)row * 32 + (rank_hi - 32)],
               (float)(row * KK + lane + 32));

    // degree + nonzero-kept count
    float v = (keep_lo ? vlo : 0.f) + (keep_hi ? vhi : 0.f);
    float c = (keep_lo && vlo != 0.f ? 1.f : 0.f) + (keep_hi && vhi != 0.f ? 1.f : 0.f);
#pragma unroll
    for (int off = 16; off; off >>= 1) {
        v += __shfl_xor_sync(0xffffffffu, v, off);
        c += __shfl_xor_sync(0xffffffffu, c, off);
    }
    if (lane == 0) atomicAdd(out + OFF_AFTER, c * (1.0f / 8192.0f));

    __syncwarp();   // order own-row zero-fill before scatter

    const float inv = 1.0f / (v + 1e-6f);
    if (keep_lo) __stcs(&out[(size_t)row * NN + nlo], vlo * inv);
    if (keep_hi) __stcs(&out[(size_t)row * NN + nhi], vhi * inv);
}

// ---------------------------------------------------------------------------
extern "C" void kernel_launch(void* const* d_in, const int* in_sizes, int n_in,
                              void* d_out, int out_size) {
    const float* adj = nullptr; const float* feat = nullptr;
    const int*   nbr = nullptr; const float* W1   = nullptr;
    const float* b1  = nullptr; const float* pa   = nullptr;
    const float* W2  = nullptr; const float* b2   = nullptr;

    for (int i = 0; i < n_in; i++) {
        long long s = in_sizes[i];
        if      (s == (long long)NN * NN) adj  = (const float*)d_in[i];
        else if (s == (long long)NN * DD) feat = (const float*)d_in[i];
        else if (s == (long long)NN * KK) nbr  = (const int*)d_in[i];
        else if (s == (long long)DD * HH) W1   = (const float*)d_in[i];
        else if (s == HH) { if (!b1) b1 = (const float*)d_in[i];
                            else     pa = (const float*)d_in[i]; }
        else if (s == HH * 2) W2 = (const float*)d_in[i];
        else if (s == 2)      b2 = (const float*)d_in[i];
    }

    float* out = (float*)d_out;
    const int k1_smem_bytes = (DD * HH + 16 * 4 * DD) * (int)sizeof(float); // 192 KB
    static int attr_done = 0;
    if (!attr_done) {
        cudaFuncSetAttribute(featw_kernel,
                             cudaFuncAttributeMaxDynamicSharedMemorySize, k1_smem_bytes);
        attr_done = 1;
    }
    featw_kernel<<<K1_BLOCKS, K1_THREADS, k1_smem_bytes>>>(feat, W1, out);
    edge_kernel<<<NN / 8, 256>>>(adj, nbr, b1, pa, W2, b2, out);
}